// round 1
// baseline (speedup 1.0000x reference)
#include <cuda_runtime.h>
#include <cuda_bf16.h>
#include <math.h>

#define FULLMASK 0xffffffffu

constexpr int T_ = 128;
constexpr int IN_ = 8;
constexpr int H_ = 128;
constexpr float EPS_ = 1e-5f;
constexpr float R2_ = 0.70710678118654752440f;

__device__ __forceinline__ float warp_sum(float v) {
    v += __shfl_xor_sync(FULLMASK, v, 16);
    v += __shfl_xor_sync(FULLMASK, v, 8);
    v += __shfl_xor_sync(FULLMASK, v, 4);
    v += __shfl_xor_sync(FULLMASK, v, 2);
    v += __shfl_xor_sync(FULLMASK, v, 1);
    return v;
}

__global__ __launch_bounds__(128, 7)
void qlstm_kernel(
    const float* __restrict__ x,     const float* __restrict__ pe,
    const float* __restrict__ emb_w, const float* __restrict__ emb_b,
    const float* __restrict__ emb_g, const float* __restrict__ emb_bt,
    const float* __restrict__ ip_w,  const float* __restrict__ ip_b,
    const float* __restrict__ in_g,  const float* __restrict__ in_b,
    const float* __restrict__ wq_i,  const float* __restrict__ wq_f,
    const float* __restrict__ wq_g,  const float* __restrict__ wq_o,
    const float* __restrict__ pi_w,  const float* __restrict__ pi_b,
    const float* __restrict__ pf_w,  const float* __restrict__ pf_b,
    const float* __restrict__ pg_w,  const float* __restrict__ pg_b,
    const float* __restrict__ po_w,  const float* __restrict__ po_b,
    const float* __restrict__ on_g,  const float* __restrict__ on_b,
    const float* __restrict__ out_w, const float* __restrict__ out_b,
    float* __restrict__ out)
{
    const int b    = blockIdx.x;
    const int tid  = threadIdx.x;      // 0..127
    const int w    = tid >> 5;         // warp: gate index (i,f,g,o)
    const int lane = tid & 31;
    const int h    = tid;              // hidden index

    __shared__ float  sh_x[T_ * IN_];        // 4 KB
    __shared__ float  sh_ipw[8 * 256];       // 8 KB
    __shared__ float  sh_pw[4][8][128];      // 16 KB  (transposed gate weights)
    __shared__ float2 sh_wcs[4][4][8];       // 1 KB   (cos/sin of weight angles/2)
    __shared__ float2 sh_incs[8];            // input angle cos/sin
    __shared__ float  sh_comb[256];
    __shared__ float  sh_z[4][8];
    __shared__ float  sh_pj[8];
    __shared__ float  sh_redA[4][2];
    __shared__ float  sh_redB[4][3];
    __shared__ float  sh_sc[2];
    __shared__ float  sh_ipb[8], sh_ing[8], sh_inb[8];

    // ---------------- init / staging ----------------
    for (int i = tid; i < T_ * IN_; i += 128) sh_x[i] = x[(size_t)b * T_ * IN_ + i];
    for (int i = tid; i < 8 * 256; i += 128)  sh_ipw[i] = ip_w[i];
    {
        const float* pw[4] = {pi_w, pf_w, pg_w, po_w};
        #pragma unroll
        for (int g = 0; g < 4; g++)
            #pragma unroll
            for (int j = 0; j < 8; j++)
                sh_pw[g][j][tid] = pw[g][tid * 8 + j];
    }
    {
        const float* wq[4] = {wq_i, wq_f, wq_g, wq_o};
        int g = tid >> 5, rem = tid & 31;
        int l = rem >> 3, q = rem & 7;
        float a = 0.5f * wq[g][l * 8 + q];
        sh_wcs[g][l][q] = make_float2(cosf(a), sinf(a));
    }
    if (tid < 8) { sh_ipb[tid] = ip_b[tid]; sh_ing[tid] = in_g[tid]; sh_inb[tid] = in_b[tid]; }

    float embw[8];
    #pragma unroll
    for (int k = 0; k < 8; k++) embw[k] = emb_w[h * 8 + k];
    const float embb  = emb_b[h], embg = emb_g[h], embbt = emb_bt[h];
    const float gw    = on_g[h] * out_w[h];
    const float bw    = on_b[h] * out_w[h];
    const float bi    = pi_b[h], bf = pf_b[h], bg = pg_b[h], bo = po_b[h];

    // S1 = sum(on_g*out_w), C0 = sum(on_b*out_w) + out_b
    {
        float s1 = warp_sum(gw), s2 = warp_sum(bw);
        if (lane == 0) { sh_redA[w][0] = s1; sh_redA[w][1] = s2; }
    }
    __syncthreads();
    if (tid == 0) {
        float S1 = 0.f, C0 = 0.f;
        #pragma unroll
        for (int i = 0; i < 4; i++) { S1 += sh_redA[i][0]; C0 += sh_redA[i][1]; }
        sh_sc[0] = S1; sh_sc[1] = C0 + out_b[0];
    }
    __syncthreads();
    const float S1 = sh_sc[0], C0 = sh_sc[1];

    // fused CNOT permutation source lanes (constant across layers)
    const int esrc = lane ^ ((lane >> 1) & 8) ^ ((lane >> 1) & 2); // ctrl0(+b7->b6), ctrl2(b5->b4)
    const int osrc = lane ^ ((lane >> 1) & 4) ^ ((lane >> 1) & 1); // ctrl1(b6->b5), ctrl3(b4->b3)
    const bool c1 = (lane & 1);                                    // ctrl4: lane bit0 -> reg bit2

    float hstate = 0.f, cstate = 0.f;
    float* outp = out + (size_t)b * T_;

    for (int t = 0; t < T_; t++) {
        // ---------- Phase A: embedding + LN + pe ----------
        float pe_v = __ldg(pe + t * H_ + h);
        float e = embb;
        #pragma unroll
        for (int k = 0; k < 8; k++) e += sh_x[t * 8 + k] * embw[k];
        {
            float s = warp_sum(e), s2 = warp_sum(e * e);
            if (lane == 0) { sh_redA[w][0] = s; sh_redA[w][1] = s2; }
        }
        __syncthreads();
        float Sv  = sh_redA[0][0] + sh_redA[1][0] + sh_redA[2][0] + sh_redA[3][0];
        float Sv2 = sh_redA[0][1] + sh_redA[1][1] + sh_redA[2][1] + sh_redA[3][1];
        float m   = Sv * (1.f / 128.f);
        float var = Sv2 * (1.f / 128.f) - m * m;
        float inv = rsqrtf(var + EPS_);
        float emb = (e - m) * inv * embg + embbt + pe_v;

        // ---------- Phase B: proj = LN(tanh(comb @ ip_w^T + b)) ----------
        sh_comb[h]       = emb;
        sh_comb[128 + h] = hstate;
        __syncthreads();
        {
            int j0 = 2 * w, j1 = j0 + 1;
            float d0 = 0.f, d1 = 0.f;
            #pragma unroll
            for (int k = 0; k < 8; k++) {
                float cv = sh_comb[k * 32 + lane];
                d0 += cv * sh_ipw[j0 * 256 + k * 32 + lane];
                d1 += cv * sh_ipw[j1 * 256 + k * 32 + lane];
            }
            d0 = warp_sum(d0); d1 = warp_sum(d1);
            if (lane == 0) { sh_pj[j0] = d0 + sh_ipb[j0]; sh_pj[j1] = d1 + sh_ipb[j1]; }
        }
        __syncthreads();
        if (w == 0) {
            float pv = tanhf(sh_pj[lane & 7]);
            float sm = pv, sq = pv * pv;
            sm += __shfl_xor_sync(FULLMASK, sm, 1); sq += __shfl_xor_sync(FULLMASK, sq, 1);
            sm += __shfl_xor_sync(FULLMASK, sm, 2); sq += __shfl_xor_sync(FULLMASK, sq, 2);
            sm += __shfl_xor_sync(FULLMASK, sm, 4); sq += __shfl_xor_sync(FULLMASK, sq, 4);
            float mm = sm * 0.125f;
            float vv = sq * 0.125f - mm * mm;
            float iv = rsqrtf(vv + EPS_);
            float pj = (pv - mm) * iv * sh_ing[lane & 7] + sh_inb[lane & 7];
            float a  = 0.5f * pj;
            if (lane < 8) sh_incs[lane] = make_float2(cosf(a), sinf(a));
        }
        __syncthreads();

        // ---------- Phase C: VQC (warp w simulates gate w) ----------
        float st[8];
        {
            float f[8][2];
            #pragma unroll
            for (int q = 0; q < 8; q++) {
                float2 cs = sh_incs[q];
                f[q][0] = R2_ * (cs.x - cs.y);
                f[q][1] = R2_ * (cs.x + cs.y);
            }
            // lane bits 0..4 -> qubits 4..0 ; reg bits 0..2 -> qubits 7..5
            float L = f[4][lane & 1] * f[3][(lane >> 1) & 1] * f[2][(lane >> 2) & 1]
                    * f[1][(lane >> 3) & 1] * f[0][(lane >> 4) & 1];
            float m00 = f[6][0] * f[7][0], m01 = f[6][0] * f[7][1];
            float m10 = f[6][1] * f[7][0], m11 = f[6][1] * f[7][1];
            float L0 = L * f[5][0], L1 = L * f[5][1];
            st[0] = L0 * m00; st[1] = L0 * m01; st[2] = L0 * m10; st[3] = L0 * m11;
            st[4] = L1 * m00; st[5] = L1 * m01; st[6] = L1 * m10; st[7] = L1 * m11;
        }

        #pragma unroll
        for (int l = 0; l < 4; l++) {
            // even CNOTs: ctrl0 + ctrl2 fused into one lane permutation
            #pragma unroll
            for (int r = 0; r < 8; r++) st[r] = __shfl_sync(FULLMASK, st[r], esrc);
            // ctrl4: lane bit0 controls reg-bit2 flip
            #pragma unroll
            for (int r = 0; r < 4; r++) {
                float a = st[r], bq = st[r + 4];
                st[r]     = c1 ? bq : a;
                st[r + 4] = c1 ? a  : bq;
            }
            // ctrl6: reg bit1 controls reg-bit0 flip (pure rename)
            { float tp = st[2]; st[2] = st[3]; st[3] = tp; tp = st[6]; st[6] = st[7]; st[7] = tp; }
            // odd CNOTs: ctrl1 + ctrl3 fused
            #pragma unroll
            for (int r = 0; r < 8; r++) st[r] = __shfl_sync(FULLMASK, st[r], osrc);
            // ctrl5: reg bit2 controls reg-bit1 flip (rename)
            { float tp = st[4]; st[4] = st[6]; st[6] = tp; tp = st[5]; st[5] = st[7]; st[7] = tp; }

            // RY on lane-bit qubits q=0..4 (mask 16,8,4,2,1)
            #pragma unroll
            for (int q = 0; q < 5; q++) {
                float2 cs = sh_wcs[w][l][q];
                const int bm = 1 << (4 - q);
                float sgn = (lane & bm) ? cs.y : -cs.y;
                #pragma unroll
                for (int r = 0; r < 8; r++) {
                    float o = __shfl_xor_sync(FULLMASK, st[r], bm);
                    st[r] = fmaf(sgn, o, cs.x * st[r]);
                }
            }
            // RY q=5 (reg bit2)
            {
                float2 cs = sh_wcs[w][l][5];
                #pragma unroll
                for (int r = 0; r < 4; r++) {
                    float a0 = st[r], a1 = st[r + 4];
                    st[r]     = cs.x * a0 - cs.y * a1;
                    st[r + 4] = cs.y * a0 + cs.x * a1;
                }
            }
            // RY q=6 (reg bit1)
            {
                float2 cs = sh_wcs[w][l][6];
                #pragma unroll
                for (int i = 0; i < 4; i++) {
                    const int base[4] = {0, 1, 4, 5};
                    int r = base[i];
                    float a0 = st[r], a1 = st[r + 2];
                    st[r]     = cs.x * a0 - cs.y * a1;
                    st[r + 2] = cs.y * a0 + cs.x * a1;
                }
            }
            // RY q=7 (reg bit0)
            {
                float2 cs = sh_wcs[w][l][7];
                #pragma unroll
                for (int r = 0; r < 8; r += 2) {
                    float a0 = st[r], a1 = st[r + 1];
                    st[r]     = cs.x * a0 - cs.y * a1;
                    st[r + 1] = cs.y * a0 + cs.x * a1;
                }
            }
        }

        // ---------- measurement: z_q = sum +-|phi|^2 ----------
        {
            float p0 = st[0]*st[0], p1 = st[1]*st[1], p2 = st[2]*st[2], p3 = st[3]*st[3];
            float p4 = st[4]*st[4], p5 = st[5]*st[5], p6 = st[6]*st[6], p7 = st[7]*st[7];
            float s01 = p0 + p1, s23 = p2 + p3, s45 = p4 + p5, s67 = p6 + p7;
            float d01 = p0 - p1, d23 = p2 - p3, d45 = p4 - p5, d67 = p6 - p7;
            float Tt = (s01 + s23) + (s45 + s67);
            float Z7 = (d01 + d23) + (d45 + d67);   // sign by state bit0 (qubit 7)
            float Z6 = (s01 - s23) + (s45 - s67);   // bit1 (qubit 6)
            float Z5 = (s01 + s23) - (s45 + s67);   // bit2 (qubit 5)
            float zq0, zq1, zq2, zq3, zq4, o;

            o = __shfl_xor_sync(FULLMASK, Tt, 1);
            zq4 = (lane & 1) ? (o - Tt) : (Tt - o); Tt += o;
            Z5 += __shfl_xor_sync(FULLMASK, Z5, 1);
            Z6 += __shfl_xor_sync(FULLMASK, Z6, 1);
            Z7 += __shfl_xor_sync(FULLMASK, Z7, 1);

            o = __shfl_xor_sync(FULLMASK, Tt, 2);
            zq3 = (lane & 2) ? (o - Tt) : (Tt - o); Tt += o;
            zq4 += __shfl_xor_sync(FULLMASK, zq4, 2);
            Z5 += __shfl_xor_sync(FULLMASK, Z5, 2);
            Z6 += __shfl_xor_sync(FULLMASK, Z6, 2);
            Z7 += __shfl_xor_sync(FULLMASK, Z7, 2);

            o = __shfl_xor_sync(FULLMASK, Tt, 4);
            zq2 = (lane & 4) ? (o - Tt) : (Tt - o); Tt += o;
            zq3 += __shfl_xor_sync(FULLMASK, zq3, 4);
            zq4 += __shfl_xor_sync(FULLMASK, zq4, 4);
            Z5 += __shfl_xor_sync(FULLMASK, Z5, 4);
            Z6 += __shfl_xor_sync(FULLMASK, Z6, 4);
            Z7 += __shfl_xor_sync(FULLMASK, Z7, 4);

            o = __shfl_xor_sync(FULLMASK, Tt, 8);
            zq1 = (lane & 8) ? (o - Tt) : (Tt - o); Tt += o;
            zq2 += __shfl_xor_sync(FULLMASK, zq2, 8);
            zq3 += __shfl_xor_sync(FULLMASK, zq3, 8);
            zq4 += __shfl_xor_sync(FULLMASK, zq4, 8);
            Z5 += __shfl_xor_sync(FULLMASK, Z5, 8);
            Z6 += __shfl_xor_sync(FULLMASK, Z6, 8);
            Z7 += __shfl_xor_sync(FULLMASK, Z7, 8);

            o = __shfl_xor_sync(FULLMASK, Tt, 16);
            zq0 = (lane & 16) ? (o - Tt) : (Tt - o);
            zq1 += __shfl_xor_sync(FULLMASK, zq1, 16);
            zq2 += __shfl_xor_sync(FULLMASK, zq2, 16);
            zq3 += __shfl_xor_sync(FULLMASK, zq3, 16);
            zq4 += __shfl_xor_sync(FULLMASK, zq4, 16);
            Z5 += __shfl_xor_sync(FULLMASK, Z5, 16);
            Z6 += __shfl_xor_sync(FULLMASK, Z6, 16);
            Z7 += __shfl_xor_sync(FULLMASK, Z7, 16);

            if (lane == 0) {
                sh_z[w][0] = zq0; sh_z[w][1] = zq1; sh_z[w][2] = zq2; sh_z[w][3] = zq3;
                sh_z[w][4] = zq4; sh_z[w][5] = Z5;  sh_z[w][6] = Z6;  sh_z[w][7] = Z7;
            }
        }
        __syncthreads();

        // ---------- Phase D: gates, LSTM update, output LN ----------
        float pre_i = bi, pre_f = bf, pre_g = bg, pre_o = bo;
        #pragma unroll
        for (int j = 0; j < 8; j++) {
            pre_i += sh_z[0][j] * sh_pw[0][j][h];
            pre_f += sh_z[1][j] * sh_pw[1][j][h];
            pre_g += sh_z[2][j] * sh_pw[2][j][h];
            pre_o += sh_z[3][j] * sh_pw[3][j][h];
        }
        float i_t = 1.f / (1.f + expf(-pre_i));
        float f_t = 1.f / (1.f + expf(-pre_f));
        float g_t = tanhf(pre_g);
        float o_t = 1.f / (1.f + expf(-pre_o));
        cstate = f_t * cstate + i_t * g_t;
        hstate = o_t * tanhf(cstate);

        float v = hstate + emb;
        {
            float r0 = warp_sum(v), r1 = warp_sum(v * v), r2 = warp_sum(v * gw);
            if (lane == 0) { sh_redB[w][0] = r0; sh_redB[w][1] = r1; sh_redB[w][2] = r2; }
        }
        __syncthreads();
        if (tid == 0) {
            float Svo = sh_redB[0][0] + sh_redB[1][0] + sh_redB[2][0] + sh_redB[3][0];
            float Sqo = sh_redB[0][1] + sh_redB[1][1] + sh_redB[2][1] + sh_redB[3][1];
            float Sgo = sh_redB[0][2] + sh_redB[1][2] + sh_redB[2][2] + sh_redB[3][2];
            float m2   = Svo * (1.f / 128.f);
            float var2 = Sqo * (1.f / 128.f) - m2 * m2;
            float inv2 = rsqrtf(var2 + EPS_);
            outp[t] = inv2 * (Sgo - m2 * S1) + C0;
        }
    }
}

extern "C" void kernel_launch(void* const* d_in, const int* in_sizes, int n_in,
                              void* d_out, int out_size) {
    const float* p[26];
    for (int i = 0; i < 26; i++) p[i] = (const float*)d_in[i];
    qlstm_kernel<<<1024, 128>>>(
        p[0], p[1], p[2], p[3], p[4], p[5], p[6], p[7], p[8], p[9],
        p[10], p[11], p[12], p[13], p[14], p[15], p[16], p[17], p[18], p[19],
        p[20], p[21], p[22], p[23], p[24], p[25],
        (float*)d_out);
}